// round 2
// baseline (speedup 1.0000x reference)
#include <cuda_runtime.h>
#include <cuda_bf16.h>
#include <math.h>

// ---------------------------------------------------------------------------
// Swin-style transformer encoder, fp32 baseline.
// B=8, H=W=64, D=512, NH=16, DK=32, WS=8, SH=4, L=4
// ---------------------------------------------------------------------------

#define BATCH 8
#define HH 64
#define WW 64
#define DIM 512
#define NHEAD 16
#define DKH 32
#define WSZ 8
#define SHF 4
#define WS2 64
#define NLAYER 4
#define NTOK (BATCH * HH * WW)          // 32768
#define SCALE 0.17677669529663687f      // 1/sqrt(32)

// Scratch buffers (no cudaMalloc allowed)
__device__ float g_xn [ (size_t)NTOK * DIM ];            // 64 MB
__device__ float g_q  [ (size_t)NTOK * DIM ];            // 64 MB
__device__ float g_kv [ (size_t)NTOK * DIM * 2 ];        // 128 MB
__device__ float g_o  [ (size_t)NTOK * DIM ];            // 64 MB
__device__ float g_mlp[ (size_t)NTOK * DIM * 4 ];        // 256 MB

// ---------------------------------------------------------------------------
// LayerNorm: one block (128 threads) per token, D=512 (4 floats/thread)
// ---------------------------------------------------------------------------
__global__ void ln_kernel(const float* __restrict__ X,
                          const float* __restrict__ gam,
                          const float* __restrict__ bet,
                          float* __restrict__ Y)
{
    __shared__ float red[8];
    int t = blockIdx.x;
    int tid = threadIdx.x;
    const float* x = X + (size_t)t * DIM;

    float4 v = *(const float4*)(x + tid * 4);
    float s  = v.x + v.y + v.z + v.w;
    float s2 = fmaf(v.x, v.x, fmaf(v.y, v.y, fmaf(v.z, v.z, v.w * v.w)));
#pragma unroll
    for (int o = 16; o > 0; o >>= 1) {
        s  += __shfl_xor_sync(0xffffffffu, s,  o);
        s2 += __shfl_xor_sync(0xffffffffu, s2, o);
    }
    int w = tid >> 5;
    if ((tid & 31) == 0) { red[w] = s; red[4 + w] = s2; }
    __syncthreads();
    s  = red[0] + red[1] + red[2] + red[3];
    s2 = red[4] + red[5] + red[6] + red[7];
    float mean = s * (1.0f / DIM);
    float var  = s2 * (1.0f / DIM) - mean * mean;
    float rstd = rsqrtf(var + 1e-5f);

    float4 gg = *(const float4*)(gam + tid * 4);
    float4 bb = *(const float4*)(bet + tid * 4);
    float4 o;
    o.x = (v.x - mean) * rstd * gg.x + bb.x;
    o.y = (v.y - mean) * rstd * gg.y + bb.y;
    o.z = (v.z - mean) * rstd * gg.z + bb.z;
    o.w = (v.w - mean) * rstd * gg.w + bb.w;
    *(float4*)(Y + (size_t)t * DIM + tid * 4) = o;
}

// ---------------------------------------------------------------------------
// SGEMM: C[M,N] = epi(A[M,K] @ B[K,N] + bias[N] (+ res[M,N]))
// Tiles: BM=128, BN=64, BK=16, 256 threads, each thread 8x4 outputs.
// EPI: 0 = bias, 1 = bias + tanh-GELU, 2 = bias + residual add
// ---------------------------------------------------------------------------
#define GBM 128
#define GBN 64
#define GBK 16

__device__ __forceinline__ float gelu_tanh(float u) {
    float t = tanhf(0.7978845608028654f * (u + 0.044715f * u * u * u));
    return 0.5f * u * (1.0f + t);
}

template<int EPI>
__global__ __launch_bounds__(256, 2)
void gemm_kernel(const float* __restrict__ A,
                 const float* __restrict__ Bw,
                 const float* __restrict__ bias,
                 const float* __restrict__ res,
                 float* __restrict__ C,
                 int M, int N, int K)
{
    __shared__ float As[GBK][GBM];
    __shared__ float Bs[GBK][GBN];

    int tid = threadIdx.x;
    int bm = blockIdx.y * GBM;
    int bn = blockIdx.x * GBN;
    int ty = tid >> 4;          // 0..15
    int tx = tid & 15;          // 0..15

    // A loader: row = tid>>2 (0..63) and +64, col4 = (tid&3)*4
    int arow = tid >> 2;
    int acol = (tid & 3) * 4;
    // B loader: brow = tid>>4 (0..15), bcol = (tid&15)*4
    int brow = tid >> 4;
    int bcol = (tid & 15) * 4;

    const float* Ap = A + (size_t)bm * K;
    float acc[8][4];
#pragma unroll
    for (int i = 0; i < 8; i++)
#pragma unroll
        for (int j = 0; j < 4; j++) acc[i][j] = 0.0f;

    for (int k0 = 0; k0 < K; k0 += GBK) {
        float4 a0 = *(const float4*)(Ap + (size_t)arow * K + k0 + acol);
        float4 a1 = *(const float4*)(Ap + (size_t)(arow + 64) * K + k0 + acol);
        As[acol + 0][arow] = a0.x;
        As[acol + 1][arow] = a0.y;
        As[acol + 2][arow] = a0.z;
        As[acol + 3][arow] = a0.w;
        As[acol + 0][arow + 64] = a1.x;
        As[acol + 1][arow + 64] = a1.y;
        As[acol + 2][arow + 64] = a1.z;
        As[acol + 3][arow + 64] = a1.w;
        *(float4*)&Bs[brow][bcol] =
            *(const float4*)(Bw + (size_t)(k0 + brow) * N + bn + bcol);
        __syncthreads();

#pragma unroll
        for (int kk = 0; kk < GBK; kk++) {
            float4 bv  = *(float4*)&Bs[kk][tx * 4];
            float4 av0 = *(float4*)&As[kk][ty * 8];
            float4 av1 = *(float4*)&As[kk][ty * 8 + 4];
            float a[8] = {av0.x, av0.y, av0.z, av0.w, av1.x, av1.y, av1.z, av1.w};
            float b[4] = {bv.x, bv.y, bv.z, bv.w};
#pragma unroll
            for (int i = 0; i < 8; i++)
#pragma unroll
                for (int j = 0; j < 4; j++)
                    acc[i][j] = fmaf(a[i], b[j], acc[i][j]);
        }
        __syncthreads();
    }

    int n0 = bn + tx * 4;
    float4 b4 = *(const float4*)(bias + n0);
#pragma unroll
    for (int i = 0; i < 8; i++) {
        int m = bm + ty * 8 + i;
        float4 o;
        o.x = acc[i][0] + b4.x;
        o.y = acc[i][1] + b4.y;
        o.z = acc[i][2] + b4.z;
        o.w = acc[i][3] + b4.w;
        if (EPI == 1) {
            o.x = gelu_tanh(o.x); o.y = gelu_tanh(o.y);
            o.z = gelu_tanh(o.z); o.w = gelu_tanh(o.w);
        }
        if (EPI == 2) {
            float4 r = *(const float4*)(res + (size_t)m * N + n0);
            o.x += r.x; o.y += r.y; o.z += r.z; o.w += r.w;
        }
        *(float4*)(C + (size_t)m * N + n0) = o;
    }
}

// ---------------------------------------------------------------------------
// Windowed attention with shift + rel-pos bias + analytic shift-mask.
// Grid: (NHEAD, 64 windows, BATCH), 256 threads.
// Q layout: [tok][head*32+d]; KV layout: [tok][{k,v}*512 + head*32 + d]
// Cyclic shift folded into gather/scatter indices.
// ---------------------------------------------------------------------------
__global__ __launch_bounds__(256)
void attn_kernel(const float* __restrict__ Q,
                 const float* __restrict__ KV,
                 const int*   __restrict__ relIdx,   // [64][64]
                 const float* __restrict__ table,    // [225][16]
                 float* __restrict__ O)
{
    __shared__ float sQ[64][33];
    __shared__ float sK[64][33];
    __shared__ float sV[64][32];
    __shared__ float sA[64][65];
    __shared__ int   sTok[64];
    __shared__ int   sLab[64];
    __shared__ float sTab[225];

    int h   = blockIdx.x;
    int win = blockIdx.y;
    int b   = blockIdx.z;
    int nwh = win >> 3, nww = win & 7;
    int tid = threadIdx.x;

    if (tid < 64) {
        int i = tid >> 3, j = tid & 7;
        int gh = (nwh * WSZ + i + SHF) & (HH - 1);
        int gw = (nww * WSZ + j + SHF) & (WW - 1);
        sTok[tid] = ((b * HH + gh) << 6) + gw;     // token index
        int ih = nwh * WSZ + i, iw = nww * WSZ + j;
        int rh = (ih >= HH - WSZ) + (ih >= HH - SHF);
        int rw = (iw >= WW - WSZ) + (iw >= WW - SHF);
        sLab[tid] = rh * 3 + rw;
    }
    if (tid < 225) sTab[tid] = table[tid * NHEAD + h];
    __syncthreads();

    // Load Q, K, V tiles (64 x 32 each)
    for (int idx = tid; idx < 64 * 8; idx += 256) {
        int row = idx >> 3;
        int c4  = (idx & 7) << 2;
        size_t qb = (size_t)sTok[row] * DIM + h * DKH + c4;
        float4 qv = *(const float4*)(Q + qb);
        sQ[row][c4 + 0] = qv.x; sQ[row][c4 + 1] = qv.y;
        sQ[row][c4 + 2] = qv.z; sQ[row][c4 + 3] = qv.w;
        size_t kb = (size_t)sTok[row] * (2 * DIM) + h * DKH + c4;
        float4 kvv = *(const float4*)(KV + kb);
        sK[row][c4 + 0] = kvv.x; sK[row][c4 + 1] = kvv.y;
        sK[row][c4 + 2] = kvv.z; sK[row][c4 + 3] = kvv.w;
        float4 vv = *(const float4*)(KV + kb + DIM);
        *(float4*)&sV[row][c4] = vv;
    }
    __syncthreads();

    // Scores + softmax.  thread -> row r = tid>>2, quad q owns cols {q,q+4,...,q+60}
    {
        int r = tid >> 2;
        int qd = tid & 3;
        float qreg[DKH];
#pragma unroll
        for (int d = 0; d < DKH; d++) qreg[d] = sQ[r][d];

        float sc[16];
        int labr = sLab[r];
        const int* ri = relIdx + r * 64;
#pragma unroll
        for (int c = 0; c < 16; c++) {
            int col = qd + (c << 2);
            float acc = 0.0f;
#pragma unroll
            for (int d = 0; d < DKH; d++)
                acc = fmaf(qreg[d], sK[col][d], acc);
            acc = acc * SCALE + sTab[ri[col]];
            if (labr != sLab[col]) acc = -1e9f;
            sc[c] = acc;
        }
        float mx = sc[0];
#pragma unroll
        for (int c = 1; c < 16; c++) mx = fmaxf(mx, sc[c]);
        mx = fmaxf(mx, __shfl_xor_sync(0xffffffffu, mx, 1));
        mx = fmaxf(mx, __shfl_xor_sync(0xffffffffu, mx, 2));
        float sum = 0.0f;
#pragma unroll
        for (int c = 0; c < 16; c++) { sc[c] = __expf(sc[c] - mx); sum += sc[c]; }
        sum += __shfl_xor_sync(0xffffffffu, sum, 1);
        sum += __shfl_xor_sync(0xffffffffu, sum, 2);
        float inv = 1.0f / sum;
#pragma unroll
        for (int c = 0; c < 16; c++) sA[r][qd + (c << 2)] = sc[c] * inv;
    }
    __syncthreads();

    // O = A @ V.  thread -> row = tid>>2, 8 dims starting at (tid&3)*8
    {
        int row = tid >> 2;
        int d0  = (tid & 3) << 3;
        float acc[8];
#pragma unroll
        for (int i = 0; i < 8; i++) acc[i] = 0.0f;
#pragma unroll
        for (int k = 0; k < 64; k++) {
            float a = sA[row][k];
            float4 v0 = *(float4*)&sV[k][d0];
            float4 v1 = *(float4*)&sV[k][d0 + 4];
            acc[0] = fmaf(a, v0.x, acc[0]);
            acc[1] = fmaf(a, v0.y, acc[1]);
            acc[2] = fmaf(a, v0.z, acc[2]);
            acc[3] = fmaf(a, v0.w, acc[3]);
            acc[4] = fmaf(a, v1.x, acc[4]);
            acc[5] = fmaf(a, v1.y, acc[5]);
            acc[6] = fmaf(a, v1.z, acc[6]);
            acc[7] = fmaf(a, v1.w, acc[7]);
        }
        size_t base = (size_t)sTok[row] * DIM + h * DKH + d0;
        *(float4*)(O + base)     = make_float4(acc[0], acc[1], acc[2], acc[3]);
        *(float4*)(O + base + 4) = make_float4(acc[4], acc[5], acc[6], acc[7]);
    }
}

// ---------------------------------------------------------------------------
// Launch
// ---------------------------------------------------------------------------
extern "C" void kernel_launch(void* const* d_in, const int* in_sizes, int n_in,
                              void* d_out, int out_size)
{
    const float* x_in      = (const float*)d_in[0];
    // d_in[1] = mask (unused; computed analytically)
    const int*   rel_index = (const int*)  d_in[2];
    const float* Wq        = (const float*)d_in[3];
    const float* bq        = (const float*)d_in[4];
    const float* Wkv       = (const float*)d_in[5];
    const float* bkv       = (const float*)d_in[6];
    const float* Wo        = (const float*)d_in[7];
    const float* bo        = (const float*)d_in[8];
    const float* rel_table = (const float*)d_in[9];
    const float* ln1_g     = (const float*)d_in[10];
    const float* ln1_b     = (const float*)d_in[11];
    const float* ln2_g     = (const float*)d_in[12];
    const float* ln2_b     = (const float*)d_in[13];
    const float* W1        = (const float*)d_in[14];
    const float* b1        = (const float*)d_in[15];
    const float* W2        = (const float*)d_in[16];
    const float* b2        = (const float*)d_in[17];

    float* xbuf = (float*)d_out;

    float *xn, *q, *kv, *o, *mlp;
    cudaGetSymbolAddress((void**)&xn,  g_xn);
    cudaGetSymbolAddress((void**)&q,   g_q);
    cudaGetSymbolAddress((void**)&kv,  g_kv);
    cudaGetSymbolAddress((void**)&o,   g_o);
    cudaGetSymbolAddress((void**)&mlp, g_mlp);

    cudaMemcpyAsync(xbuf, x_in, (size_t)NTOK * DIM * sizeof(float),
                    cudaMemcpyDeviceToDevice);

    dim3 gLN(NTOK), bLN(128);
    dim3 bG(256);
    dim3 gAttn(NHEAD, 64, BATCH), bAttn(256);

    for (int l = 0; l < NLAYER; l++) {
        const float* wq  = Wq  + (size_t)l * DIM * DIM;
        const float* bqv = bq  + (size_t)l * DIM;
        const float* wkv = Wkv + (size_t)l * DIM * 2 * DIM;
        const float* bkvv= bkv + (size_t)l * 2 * DIM;
        const float* wo  = Wo  + (size_t)l * DIM * DIM;
        const float* bov = bo  + (size_t)l * DIM;
        const float* tab = rel_table + (size_t)l * 225 * NHEAD;
        const float* w1  = W1  + (size_t)l * DIM * 4 * DIM;
        const float* b1v = b1  + (size_t)l * 4 * DIM;
        const float* w2  = W2  + (size_t)l * 4 * DIM * DIM;
        const float* b2v = b2  + (size_t)l * DIM;

        // xn = LN1(x)
        ln_kernel<<<gLN, bLN>>>(xbuf, ln1_g + (size_t)l * DIM,
                                ln1_b + (size_t)l * DIM, xn);
        // Q = xn @ Wq + bq
        gemm_kernel<0><<<dim3(DIM / GBN, NTOK / GBM), bG>>>(
            xn, wq, bqv, nullptr, q, NTOK, DIM, DIM);
        // KV = xn @ Wkv + bkv
        gemm_kernel<0><<<dim3(2 * DIM / GBN, NTOK / GBM), bG>>>(
            xn, wkv, bkvv, nullptr, kv, NTOK, 2 * DIM, DIM);
        // windowed attention
        attn_kernel<<<gAttn, bAttn>>>(q, kv, rel_index, tab, o);
        // x = x + O @ Wo + bo
        gemm_kernel<2><<<dim3(DIM / GBN, NTOK / GBM), bG>>>(
            o, wo, bov, xbuf, xbuf, NTOK, DIM, DIM);
        // h = LN2(x)
        ln_kernel<<<gLN, bLN>>>(xbuf, ln2_g + (size_t)l * DIM,
                                ln2_b + (size_t)l * DIM, xn);
        // mlp = gelu(h @ W1 + b1)
        gemm_kernel<1><<<dim3(4 * DIM / GBN, NTOK / GBM), bG>>>(
            xn, w1, b1v, nullptr, mlp, NTOK, 4 * DIM, DIM);
        // x = x + mlp @ W2 + b2
        gemm_kernel<2><<<dim3(DIM / GBN, NTOK / GBM), bG>>>(
            mlp, w2, b2v, xbuf, xbuf, NTOK, DIM, 4 * DIM);
    }
}

// round 5
// speedup vs baseline: 2.3087x; 2.3087x over previous
#include <cuda_runtime.h>
#include <cuda_bf16.h>
#include <math.h>
#include <stdint.h>

// ---------------------------------------------------------------------------
// Swin-style transformer encoder. mma.sync bf16x3-split GEMMs (sm_103-safe).
// B=8, H=W=64, D=512, NH=16, DK=32, WS=8, SH=4, L=4
// ---------------------------------------------------------------------------

#define BATCH 8
#define HH 64
#define WW 64
#define DIM 512
#define NHEAD 16
#define DKH 32
#define WSZ 8
#define SHF 4
#define NLAYER 4
#define NTOK (BATCH * HH * WW)          // 32768
#define SCALE 0.17677669529663687f     // 1/sqrt(32)

// Transposed-weight offsets (elements) within one layer's block
#define WOFF_Q  0
#define WOFF_KV 262144
#define WOFF_O  786432
#define WOFF_W1 1048576
#define WOFF_W2 2097152
#define WLAYER  3145728

// ---------------------------------------------------------------------------
// Scratch (__device__ globals; no allocation allowed)
// ---------------------------------------------------------------------------
__device__ __nv_bfloat16 g_xnh[(size_t)NTOK * DIM];
__device__ __nv_bfloat16 g_xnl[(size_t)NTOK * DIM];
__device__ float         g_q  [(size_t)NTOK * DIM];
__device__ float         g_kv [(size_t)NTOK * DIM * 2];
__device__ __nv_bfloat16 g_oh [(size_t)NTOK * DIM];
__device__ __nv_bfloat16 g_ol [(size_t)NTOK * DIM];
__device__ __nv_bfloat16 g_mh [(size_t)NTOK * DIM * 4];
__device__ __nv_bfloat16 g_ml [(size_t)NTOK * DIM * 4];
__device__ __nv_bfloat16 g_wth[(size_t)NLAYER * WLAYER];
__device__ __nv_bfloat16 g_wtl[(size_t)NLAYER * WLAYER];

// ---------------------------------------------------------------------------
// Helpers
// ---------------------------------------------------------------------------
__device__ __forceinline__ uint32_t smem_u32(const void* p) {
    uint32_t a;
    asm("{ .reg .u64 t; cvta.to.shared.u64 t, %1; cvt.u32.u64 %0, t; }"
        : "=r"(a) : "l"(p));
    return a;
}
__device__ __forceinline__ void cpa16(uint32_t dst, const void* src) {
    asm volatile("cp.async.cg.shared.global [%0], [%1], 16;" :: "r"(dst), "l"(src));
}
__device__ __forceinline__ void ldsm_x4(uint32_t* r, uint32_t addr) {
    asm volatile("ldmatrix.sync.aligned.m8n8.x4.shared.b16 {%0,%1,%2,%3}, [%4];"
                 : "=r"(r[0]), "=r"(r[1]), "=r"(r[2]), "=r"(r[3]) : "r"(addr));
}
__device__ __forceinline__ void mma16816(float* d, const uint32_t* a, const uint32_t* b) {
    asm volatile("mma.sync.aligned.m16n8k16.row.col.f32.bf16.bf16.f32 "
        "{%0,%1,%2,%3}, {%4,%5,%6,%7}, {%8,%9}, {%0,%1,%2,%3};"
        : "+f"(d[0]), "+f"(d[1]), "+f"(d[2]), "+f"(d[3])
        : "r"(a[0]), "r"(a[1]), "r"(a[2]), "r"(a[3]), "r"(b[0]), "r"(b[1]));
}
__device__ __forceinline__ void bfsplit(float v, unsigned short& hi, unsigned short& lo) {
    __nv_bfloat16 hb = __float2bfloat16(v);
    hi = __bfloat16_as_ushort(hb);
    lo = __bfloat16_as_ushort(__float2bfloat16(v - __bfloat162float(hb)));
}
__device__ __forceinline__ float gelu_tanh(float u) {
    float t = tanhf(0.7978845608028654f * (u + 0.044715f * u * u * u));
    return 0.5f * u * (1.0f + t);
}

// ---------------------------------------------------------------------------
// Weight transform: W[K,N] fp32 -> Wt_hi[N,K], Wt_lo[N,K] bf16
// ---------------------------------------------------------------------------
__global__ void wtrans_kernel(const float* __restrict__ W,
                              __nv_bfloat16* __restrict__ Th,
                              __nv_bfloat16* __restrict__ Tl,
                              int K, int N)
{
    __shared__ float t[32][33];
    int nb = blockIdx.x * 32, kb = blockIdx.y * 32;
    int tx = threadIdx.x & 31, ty = threadIdx.x >> 5;
#pragma unroll
    for (int i = 0; i < 32; i += 8)
        t[ty + i][tx] = W[(size_t)(kb + ty + i) * N + nb + tx];
    __syncthreads();
#pragma unroll
    for (int i = 0; i < 32; i += 8) {
        float v = t[tx][ty + i];
        unsigned short hi, lo;
        bfsplit(v, hi, lo);
        size_t idx = (size_t)(nb + ty + i) * K + kb + tx;
        Th[idx] = __ushort_as_bfloat16(hi);
        Tl[idx] = __ushort_as_bfloat16(lo);
    }
}

// ---------------------------------------------------------------------------
// LayerNorm -> bf16 hi/lo
// ---------------------------------------------------------------------------
__global__ void ln_kernel(const float* __restrict__ X,
                          const float* __restrict__ gam,
                          const float* __restrict__ bet,
                          __nv_bfloat16* __restrict__ Yh,
                          __nv_bfloat16* __restrict__ Yl)
{
    __shared__ float red[8];
    int t = blockIdx.x;
    int tid = threadIdx.x;
    const float* x = X + (size_t)t * DIM;

    float4 v = *(const float4*)(x + tid * 4);
    float s  = v.x + v.y + v.z + v.w;
    float s2 = fmaf(v.x, v.x, fmaf(v.y, v.y, fmaf(v.z, v.z, v.w * v.w)));
#pragma unroll
    for (int o = 16; o > 0; o >>= 1) {
        s  += __shfl_xor_sync(0xffffffffu, s,  o);
        s2 += __shfl_xor_sync(0xffffffffu, s2, o);
    }
    int w = tid >> 5;
    if ((tid & 31) == 0) { red[w] = s; red[4 + w] = s2; }
    __syncthreads();
    s  = red[0] + red[1] + red[2] + red[3];
    s2 = red[4] + red[5] + red[6] + red[7];
    float mean = s * (1.0f / DIM);
    float var  = s2 * (1.0f / DIM) - mean * mean;
    float rstd = rsqrtf(var + 1e-5f);

    float4 gg = *(const float4*)(gam + tid * 4);
    float4 bb = *(const float4*)(bet + tid * 4);
    float o0 = (v.x - mean) * rstd * gg.x + bb.x;
    float o1 = (v.y - mean) * rstd * gg.y + bb.y;
    float o2 = (v.z - mean) * rstd * gg.z + bb.z;
    float o3 = (v.w - mean) * rstd * gg.w + bb.w;

    unsigned short h0,h1,h2,h3,l0,l1,l2,l3;
    bfsplit(o0,h0,l0); bfsplit(o1,h1,l1); bfsplit(o2,h2,l2); bfsplit(o3,h3,l3);
    uint2 uh = make_uint2((uint32_t)h0 | ((uint32_t)h1 << 16),
                          (uint32_t)h2 | ((uint32_t)h3 << 16));
    uint2 ul = make_uint2((uint32_t)l0 | ((uint32_t)l1 << 16),
                          (uint32_t)l2 | ((uint32_t)l3 << 16));
    size_t base = (size_t)t * DIM + tid * 4;
    *(uint2*)(Yh + base) = uh;
    *(uint2*)(Yl + base) = ul;
}

// ---------------------------------------------------------------------------
// mma.sync GEMM: C[M,N] = epi(Ahl[M,K] @ Bhl[N,K]^T + bias)
// Tile 128x128x32, 8 warps (4x2, each 32x64), 3-stage cp.async, bf16x3 split.
// EPI: 0 = bias->fp32   1 = bias+gelu->bf16 hi/lo   2 = bias+res->fp32
// smem per stage: Ah 8K | Al 8K | Bh 8K | Bl 8K = 32KB.  3 stages + 512B bias.
// Swizzle: 16B seg s of row r stored at seg (s ^ ((r>>1)&3)).
// ---------------------------------------------------------------------------
#define MG_STAGE 32768
#define MG_SMEM  (3 * MG_STAGE + 512)

__device__ __forceinline__ void mg_load_chunk(
    uint32_t st,
    const __nv_bfloat16* __restrict__ Ah, const __nv_bfloat16* __restrict__ Al,
    const __nv_bfloat16* __restrict__ Bh, const __nv_bfloat16* __restrict__ Bl,
    int bm, int bn, int K, int k0, int tid)
{
#pragma unroll
    for (int i = 0; i < 2; i++) {
        int ch = tid + (i << 8);
        int r  = ch >> 2;
        int s  = ch & 3;
        uint32_t off = (uint32_t)(r * 64) + (uint32_t)((s ^ ((r >> 1) & 3)) << 4);
        size_t ga = (size_t)(bm + r) * K + k0 + s * 8;
        size_t gb = (size_t)(bn + r) * K + k0 + s * 8;
        cpa16(st + off,         Ah + ga);
        cpa16(st + 8192  + off, Al + ga);
        cpa16(st + 16384 + off, Bh + gb);
        cpa16(st + 24576 + off, Bl + gb);
    }
}

template<int EPI>
__global__ __launch_bounds__(256, 1)
void mg_gemm(const __nv_bfloat16* __restrict__ Ah, const __nv_bfloat16* __restrict__ Al,
             const __nv_bfloat16* __restrict__ Bh, const __nv_bfloat16* __restrict__ Bl,
             const float* __restrict__ bias, const float* __restrict__ res,
             float* __restrict__ outF,
             __nv_bfloat16* __restrict__ outH, __nv_bfloat16* __restrict__ outL,
             int M, int N, int K)
{
    extern __shared__ __align__(1024) char smem[];
    const int tid  = threadIdx.x;
    const int lane = tid & 31;
    const int wid  = tid >> 5;
    const int wm   = wid & 3;          // 0..3 -> m offset 32*wm
    const int wn   = wid >> 2;         // 0..1 -> n offset 64*wn
    const int bm = blockIdx.y * 128, bn = blockIdx.x * 128;

    float* sbias = (float*)(smem + 3 * MG_STAGE);
    if (tid < 32)
        ((float4*)sbias)[tid] = ((const float4*)(bias + bn))[tid];

    uint32_t sb = smem_u32(smem);

    float acc[2][8][4];
#pragma unroll
    for (int mi = 0; mi < 2; mi++)
#pragma unroll
        for (int ni = 0; ni < 8; ni++)
#pragma unroll
            for (int j = 0; j < 4; j++) acc[mi][ni][j] = 0.0f;

    const int nch = K >> 5;

    mg_load_chunk(sb, Ah, Al, Bh, Bl, bm, bn, K, 0, tid);
    asm volatile("cp.async.commit_group;");
    if (nch > 1)
        mg_load_chunk(sb + MG_STAGE, Ah, Al, Bh, Bl, bm, bn, K, 32, tid);
    asm volatile("cp.async.commit_group;");

    // Precompute ldmatrix lane addressing pieces
    const int j8  = lane & 7;
    // A: row = wm*32 + mi*16 + (j&7) + ((j>>3)&1)*8 ; seg = kk*2 + (j>>4)
    const int a_row_off = wm * 32 + j8 + ((lane >> 3) & 1) * 8;
    const int a_seg_off = (lane >> 4);               // 0/1
    // B: row = wn*64 + pi*16 + (j&7) + ((j>>4)&1)*8 ; seg = kk*2 + ((j>>3)&1)
    const int b_row_off = wn * 64 + j8 + ((lane >> 4) & 1) * 8;
    const int b_seg_off = ((lane >> 3) & 1);

    for (int c = 0; c < nch; c++) {
        asm volatile("cp.async.wait_group 1;");
        __syncthreads();

        // issue load for chunk c+2 into stage (c+2)%3 (empty commit at tail)
        if (c + 2 < nch)
            mg_load_chunk(sb + (uint32_t)((c + 2) % 3) * MG_STAGE,
                          Ah, Al, Bh, Bl, bm, bn, K, (c + 2) << 5, tid);
        asm volatile("cp.async.commit_group;");

        uint32_t st = sb + (uint32_t)(c % 3) * MG_STAGE;

#pragma unroll
        for (int kk = 0; kk < 2; kk++) {
            uint32_t a_hi[2][4], a_lo[2][4];
#pragma unroll
            for (int mi = 0; mi < 2; mi++) {
                int row = a_row_off + mi * 16;
                int seg = kk * 2 + a_seg_off;
                uint32_t off = (uint32_t)(row * 64) +
                               (uint32_t)((seg ^ ((row >> 1) & 3)) << 4);
                ldsm_x4(a_hi[mi], st + off);
                ldsm_x4(a_lo[mi], st + 8192 + off);
            }
            uint32_t b_hi[4][4], b_lo[4][4];
#pragma unroll
            for (int pi = 0; pi < 4; pi++) {
                int row = b_row_off + pi * 16;
                int seg = kk * 2 + b_seg_off;
                uint32_t off = (uint32_t)(row * 64) +
                               (uint32_t)((seg ^ ((row >> 1) & 3)) << 4);
                ldsm_x4(b_hi[pi], st + 16384 + off);
                ldsm_x4(b_lo[pi], st + 24576 + off);
            }
#pragma unroll
            for (int mi = 0; mi < 2; mi++)
#pragma unroll
                for (int ni = 0; ni < 8; ni++) {
                    const uint32_t* bh = &b_hi[ni >> 1][(ni & 1) * 2];
                    const uint32_t* bl = &b_lo[ni >> 1][(ni & 1) * 2];
                    mma16816(acc[mi][ni], a_hi[mi], bh);
                    mma16816(acc[mi][ni], a_hi[mi], bl);
                    mma16816(acc[mi][ni], a_lo[mi], bh);
                }
        }
        // no sync needed here: next-iter wait_group+syncthreads precedes reuse
    }
    __syncthreads();

    // Epilogue: acc[mi][ni] regs {r0,r1} row base+lane/4, {r2,r3} row +8,
    // cols = wn*64 + ni*8 + 2*(lane&3) + {0,1}
#pragma unroll
    for (int mi = 0; mi < 2; mi++) {
        int r0 = bm + wm * 32 + mi * 16 + (lane >> 2);
#pragma unroll
        for (int ni = 0; ni < 8; ni++) {
            int cb = wn * 64 + ni * 8 + 2 * (lane & 3);
            float bv0 = sbias[cb], bv1 = sbias[cb + 1];
            float v0 = acc[mi][ni][0] + bv0;
            float v1 = acc[mi][ni][1] + bv1;
            float v2 = acc[mi][ni][2] + bv0;
            float v3 = acc[mi][ni][3] + bv1;
            size_t g0 = (size_t)r0 * N + bn + cb;
            size_t g1 = (size_t)(r0 + 8) * N + bn + cb;
            if (EPI == 0) {
                *(float2*)(outF + g0) = make_float2(v0, v1);
                *(float2*)(outF + g1) = make_float2(v2, v3);
            } else if (EPI == 2) {
                float2 q0 = *(const float2*)(res + g0);
                float2 q1 = *(const float2*)(res + g1);
                *(float2*)(outF + g0) = make_float2(v0 + q0.x, v1 + q0.y);
                *(float2*)(outF + g1) = make_float2(v2 + q1.x, v3 + q1.y);
            } else {
                v0 = gelu_tanh(v0); v1 = gelu_tanh(v1);
                v2 = gelu_tanh(v2); v3 = gelu_tanh(v3);
                unsigned short h0,h1,h2,h3,l0,l1,l2,l3;
                bfsplit(v0,h0,l0); bfsplit(v1,h1,l1);
                bfsplit(v2,h2,l2); bfsplit(v3,h3,l3);
                *(uint32_t*)(outH + g0) = (uint32_t)h0 | ((uint32_t)h1 << 16);
                *(uint32_t*)(outH + g1) = (uint32_t)h2 | ((uint32_t)h3 << 16);
                *(uint32_t*)(outL + g0) = (uint32_t)l0 | ((uint32_t)l1 << 16);
                *(uint32_t*)(outL + g1) = (uint32_t)l2 | ((uint32_t)l3 << 16);
            }
        }
    }
}

// ---------------------------------------------------------------------------
// Windowed attention (fp32 in, bf16 hi/lo out)
// ---------------------------------------------------------------------------
__global__ __launch_bounds__(256)
void attn_kernel(const float* __restrict__ Q,
                 const float* __restrict__ KV,
                 const int*   __restrict__ relIdx,
                 const float* __restrict__ table,
                 __nv_bfloat16* __restrict__ Oh,
                 __nv_bfloat16* __restrict__ Ol)
{
    __shared__ float sQ[64][33];
    __shared__ float sK[64][33];
    __shared__ float sV[64][32];
    __shared__ float sA[64][65];
    __shared__ int   sTok[64];
    __shared__ int   sLab[64];
    __shared__ float sTab[225];

    int h   = blockIdx.x;
    int win = blockIdx.y;
    int b   = blockIdx.z;
    int nwh = win >> 3, nww = win & 7;
    int tid = threadIdx.x;

    if (tid < 64) {
        int i = tid >> 3, j = tid & 7;
        int gh = (nwh * WSZ + i + SHF) & (HH - 1);
        int gw = (nww * WSZ + j + SHF) & (WW - 1);
        sTok[tid] = ((b * HH + gh) << 6) + gw;
        int ih = nwh * WSZ + i, iw = nww * WSZ + j;
        int rh = (ih >= HH - WSZ) + (ih >= HH - SHF);
        int rw = (iw >= WW - WSZ) + (iw >= WW - SHF);
        sLab[tid] = rh * 3 + rw;
    }
    if (tid < 225) sTab[tid] = table[tid * NHEAD + h];
    __syncthreads();

    for (int idx = tid; idx < 64 * 8; idx += 256) {
        int row = idx >> 3;
        int c4  = (idx & 7) << 2;
        size_t qb = (size_t)sTok[row] * DIM + h * DKH + c4;
        float4 qv = *(const float4*)(Q + qb);
        sQ[row][c4 + 0] = qv.x; sQ[row][c4 + 1] = qv.y;
        sQ[row][c4 + 2] = qv.z; sQ[row][c4 + 3] = qv.w;
        size_t kb = (size_t)sTok[row] * (2 * DIM) + h * DKH + c4;
        float4 kvv = *(const float4*)(KV + kb);
        sK[row][c4 + 0] = kvv.x; sK[row][c4 + 1] = kvv.y;
        sK[row][c4 + 2] = kvv.z; sK[row][c4 + 3] = kvv.w;
        float4 vv = *(const float4*)(KV + kb + DIM);
        *(float4*)&sV[row][c4] = vv;
    }
    __syncthreads();

    {
        int r = tid >> 2;
        int qd = tid & 3;
        float qreg[DKH];
#pragma unroll
        for (int d = 0; d < DKH; d++) qreg[d] = sQ[r][d];

        float sc[16];
        int labr = sLab[r];
        const int* ri = relIdx + r * 64;
#pragma unroll
        for (int c = 0; c < 16; c++) {
            int col = qd + (c << 2);
            float a = 0.0f;
#pragma unroll
            for (int d = 0; d < DKH; d++)
                a = fmaf(qreg[d], sK[col][d], a);
            a = a * SCALE + sTab[ri[col]];
            if (labr != sLab[col]) a = -1e9f;
            sc[c] = a;
        }
        float mx = sc[0];
#pragma unroll
        for (int c = 1; c < 16; c++) mx = fmaxf(mx, sc[c]);
        mx = fmaxf(mx, __shfl_xor_sync(0xffffffffu, mx, 1));
        mx = fmaxf(mx, __shfl_xor_sync(0xffffffffu, mx, 2));
        float sum = 0.0f;
#pragma unroll
        for (int c = 0; c < 16; c++) { sc[c] = __expf(sc[c] - mx); sum += sc[c]; }
        sum += __shfl_xor_sync(0xffffffffu, sum, 1);
        sum += __shfl_xor_sync(0xffffffffu, sum, 2);
        float inv = 1.0f / sum;
#pragma unroll
        for (int c = 0; c < 16; c++) sA[r][qd + (c << 2)] = sc[c] * inv;
    }
    __syncthreads();

    {
        int row = tid >> 2;
        int d0  = (tid & 3) << 3;
        float a8[8];
#pragma unroll
        for (int i = 0; i < 8; i++) a8[i] = 0.0f;
#pragma unroll
        for (int k = 0; k < 64; k++) {
            float a = sA[row][k];
            float4 v0 = *(float4*)&sV[k][d0];
            float4 v1 = *(float4*)&sV[k][d0 + 4];
            a8[0] = fmaf(a, v0.x, a8[0]);
            a8[1] = fmaf(a, v0.y, a8[1]);
            a8[2] = fmaf(a, v0.z, a8[2]);
            a8[3] = fmaf(a, v0.w, a8[3]);
            a8[4] = fmaf(a, v1.x, a8[4]);
            a8[5] = fmaf(a, v1.y, a8[5]);
            a8[6] = fmaf(a, v1.z, a8[6]);
            a8[7] = fmaf(a, v1.w, a8[7]);
        }
        unsigned short hb[8], lb[8];
#pragma unroll
        for (int i = 0; i < 8; i++) bfsplit(a8[i], hb[i], lb[i]);
        size_t base = (size_t)sTok[row] * DIM + h * DKH + d0;
        *(uint2*)(Oh + base) = make_uint2((uint32_t)hb[0] | ((uint32_t)hb[1]<<16),
                                          (uint32_t)hb[2] | ((uint32_t)hb[3]<<16));
        *(uint2*)(Oh + base + 4) = make_uint2((uint32_t)hb[4] | ((uint32_t)hb[5]<<16),
                                              (uint32_t)hb[6] | ((uint32_t)hb[7]<<16));
        *(uint2*)(Ol + base) = make_uint2((uint32_t)lb[0] | ((uint32_t)lb[1]<<16),
                                          (uint32_t)lb[2] | ((uint32_t)lb[3]<<16));
        *(uint2*)(Ol + base + 4) = make_uint2((uint32_t)lb[4] | ((uint32_t)lb[5]<<16),
                                              (uint32_t)lb[6] | ((uint32_t)lb[7]<<16));
    }
}

// ---------------------------------------------------------------------------
// Launch
// ---------------------------------------------------------------------------
extern "C" void kernel_launch(void* const* d_in, const int* in_sizes, int n_in,
                              void* d_out, int out_size)
{
    const float* x_in      = (const float*)d_in[0];
    const int*   rel_index = (const int*)  d_in[2];
    const float* Wq        = (const float*)d_in[3];
    const float* bq        = (const float*)d_in[4];
    const float* Wkv       = (const float*)d_in[5];
    const float* bkv       = (const float*)d_in[6];
    const float* Wo        = (const float*)d_in[7];
    const float* bo        = (const float*)d_in[8];
    const float* rel_table = (const float*)d_in[9];
    const float* ln1_g     = (const float*)d_in[10];
    const float* ln1_b     = (const float*)d_in[11];
    const float* ln2_g     = (const float*)d_in[12];
    const float* ln2_b     = (const float*)d_in[13];
    const float* W1        = (const float*)d_in[14];
    const float* b1        = (const float*)d_in[15];
    const float* W2        = (const float*)d_in[16];
    const float* b2        = (const float*)d_in[17];

    float* xbuf = (float*)d_out;

    __nv_bfloat16 *xnh, *xnl, *oh, *ol, *mh, *ml, *wth, *wtl;
    float *q, *kv;
    cudaGetSymbolAddress((void**)&xnh, g_xnh);
    cudaGetSymbolAddress((void**)&xnl, g_xnl);
    cudaGetSymbolAddress((void**)&q,   g_q);
    cudaGetSymbolAddress((void**)&kv,  g_kv);
    cudaGetSymbolAddress((void**)&oh,  g_oh);
    cudaGetSymbolAddress((void**)&ol,  g_ol);
    cudaGetSymbolAddress((void**)&mh,  g_mh);
    cudaGetSymbolAddress((void**)&ml,  g_ml);
    cudaGetSymbolAddress((void**)&wth, g_wth);
    cudaGetSymbolAddress((void**)&wtl, g_wtl);

    cudaFuncSetAttribute(mg_gemm<0>, cudaFuncAttributeMaxDynamicSharedMemorySize, MG_SMEM);
    cudaFuncSetAttribute(mg_gemm<1>, cudaFuncAttributeMaxDynamicSharedMemorySize, MG_SMEM);
    cudaFuncSetAttribute(mg_gemm<2>, cudaFuncAttributeMaxDynamicSharedMemorySize, MG_SMEM);

    cudaMemcpyAsync(xbuf, x_in, (size_t)NTOK * DIM * sizeof(float),
                    cudaMemcpyDeviceToDevice);

    // Weight transform (all layers)
    for (int l = 0; l < NLAYER; l++) {
        size_t lw = (size_t)l * WLAYER;
        wtrans_kernel<<<dim3(512/32, 512/32), 256>>>(
            Wq + (size_t)l*DIM*DIM, wth + lw + WOFF_Q, wtl + lw + WOFF_Q, 512, 512);
        wtrans_kernel<<<dim3(1024/32, 512/32), 256>>>(
            Wkv + (size_t)l*DIM*2*DIM, wth + lw + WOFF_KV, wtl + lw + WOFF_KV, 512, 1024);
        wtrans_kernel<<<dim3(512/32, 512/32), 256>>>(
            Wo + (size_t)l*DIM*DIM, wth + lw + WOFF_O, wtl + lw + WOFF_O, 512, 512);
        wtrans_kernel<<<dim3(2048/32, 512/32), 256>>>(
            W1 + (size_t)l*DIM*4*DIM, wth + lw + WOFF_W1, wtl + lw + WOFF_W1, 512, 2048);
        wtrans_kernel<<<dim3(512/32, 2048/32), 256>>>(
            W2 + (size_t)l*4*DIM*DIM, wth + lw + WOFF_W2, wtl + lw + WOFF_W2, 2048, 512);
    }

    dim3 gLN(NTOK), bLN(128);
    dim3 gAttn(NHEAD, 64, BATCH), bAttn(256);

    for (int l = 0; l < NLAYER; l++) {
        size_t lw = (size_t)l * WLAYER;
        const float* bqv  = bq  + (size_t)l * DIM;
        const float* bkvv = bkv + (size_t)l * 2 * DIM;
        const float* bov  = bo  + (size_t)l * DIM;
        const float* tab  = rel_table + (size_t)l * 225 * NHEAD;
        const float* b1v  = b1  + (size_t)l * 4 * DIM;
        const float* b2v  = b2  + (size_t)l * DIM;

        ln_kernel<<<gLN, bLN>>>(xbuf, ln1_g + (size_t)l*DIM, ln1_b + (size_t)l*DIM,
                                xnh, xnl);
        mg_gemm<0><<<dim3(4, 256), 256, MG_SMEM>>>(
            xnh, xnl, wth + lw + WOFF_Q, wtl + lw + WOFF_Q,
            bqv, nullptr, q, nullptr, nullptr, NTOK, 512, 512);
        mg_gemm<0><<<dim3(8, 256), 256, MG_SMEM>>>(
            xnh, xnl, wth + lw + WOFF_KV, wtl + lw + WOFF_KV,
            bkvv, nullptr, kv, nullptr, nullptr, NTOK, 1024, 512);
        attn_kernel<<<gAttn, bAttn>>>(q, kv, rel_index, tab, oh, ol);
        mg_gemm<2><<<dim3(4, 256), 256, MG_SMEM>>>(
            oh, ol, wth + lw + WOFF_O, wtl + lw + WOFF_O,
            bov, xbuf, xbuf, nullptr, nullptr, NTOK, 512, 512);
        ln_kernel<<<gLN, bLN>>>(xbuf, ln2_g + (size_t)l*DIM, ln2_b + (size_t)l*DIM,
                                xnh, xnl);
        mg_gemm<1><<<dim3(16, 256), 256, MG_SMEM>>>(
            xnh, xnl, wth + lw + WOFF_W1, wtl + lw + WOFF_W1,
            b1v, nullptr, nullptr, mh, ml, NTOK, 2048, 512);
        mg_gemm<2><<<dim3(4, 256), 256, MG_SMEM>>>(
            mh, ml, wth + lw + WOFF_W2, wtl + lw + WOFF_W2,
            b2v, xbuf, xbuf, nullptr, nullptr, NTOK, 512, 2048);
    }
}

// round 6
// speedup vs baseline: 4.9992x; 2.1653x over previous
#include <cuda_runtime.h>
#include <cuda_fp16.h>
#include <math.h>
#include <stdint.h>

// ---------------------------------------------------------------------------
// Swin-style transformer encoder. mma.sync fp16 GEMMs (sm_103-safe).
// B=8, H=W=64, D=512, NH=16, DK=32, WS=8, SH=4, L=4
// ---------------------------------------------------------------------------

#define BATCH 8
#define HH 64
#define WW 64
#define DIM 512
#define NHEAD 16
#define DKH 32
#define WSZ 8
#define SHF 4
#define NLAYER 4
#define NTOK (BATCH * HH * WW)          // 32768
#define SCALE 0.17677669529663687f     // 1/sqrt(32)

// Transposed-weight offsets (elements) within one layer's block
#define WOFF_Q  0
#define WOFF_KV 262144
#define WOFF_O  786432
#define WOFF_W1 1048576
#define WOFF_W2 2097152
#define WLAYER  3145728

// ---------------------------------------------------------------------------
// Scratch (__device__ globals; no allocation allowed)
// ---------------------------------------------------------------------------
__device__ __half g_xn [(size_t)NTOK * DIM];
__device__ float  g_q  [(size_t)NTOK * DIM];
__device__ float  g_kv [(size_t)NTOK * DIM * 2];
__device__ __half g_o  [(size_t)NTOK * DIM];
__device__ __half g_m  [(size_t)NTOK * DIM * 4];
__device__ __half g_wt [(size_t)NLAYER * WLAYER];

// ---------------------------------------------------------------------------
// Helpers
// ---------------------------------------------------------------------------
__device__ __forceinline__ uint32_t smem_u32(const void* p) {
    uint32_t a;
    asm("{ .reg .u64 t; cvta.to.shared.u64 t, %1; cvt.u32.u64 %0, t; }"
        : "=r"(a) : "l"(p));
    return a;
}
__device__ __forceinline__ void cpa16(uint32_t dst, const void* src) {
    asm volatile("cp.async.cg.shared.global [%0], [%1], 16;" :: "r"(dst), "l"(src));
}
__device__ __forceinline__ void ldsm_x4(uint32_t* r, uint32_t addr) {
    asm volatile("ldmatrix.sync.aligned.m8n8.x4.shared.b16 {%0,%1,%2,%3}, [%4];"
                 : "=r"(r[0]), "=r"(r[1]), "=r"(r[2]), "=r"(r[3]) : "r"(addr));
}
__device__ __forceinline__ void mma16816(float* d, const uint32_t* a, const uint32_t* b) {
    asm volatile("mma.sync.aligned.m16n8k16.row.col.f32.f16.f16.f32 "
        "{%0,%1,%2,%3}, {%4,%5,%6,%7}, {%8,%9}, {%0,%1,%2,%3};"
        : "+f"(d[0]), "+f"(d[1]), "+f"(d[2]), "+f"(d[3])
        : "r"(a[0]), "r"(a[1]), "r"(a[2]), "r"(a[3]), "r"(b[0]), "r"(b[1]));
}
__device__ __forceinline__ float gelu_tanh(float u) {
    float t = tanhf(0.7978845608028654f * (u + 0.044715f * u * u * u));
    return 0.5f * u * (1.0f + t);
}
__device__ __forceinline__ uint32_t pack_h2(float a, float b) {
    __half2 h = __floats2half2_rn(a, b);
    return *(uint32_t*)&h;
}

// ---------------------------------------------------------------------------
// Weight transform: W[K,N] fp32 -> Wt[N,K] fp16
// ---------------------------------------------------------------------------
__global__ void wtrans_kernel(const float* __restrict__ W,
                              __half* __restrict__ T,
                              int K, int N)
{
    __shared__ float t[32][33];
    int nb = blockIdx.x * 32, kb = blockIdx.y * 32;
    int tx = threadIdx.x & 31, ty = threadIdx.x >> 5;
#pragma unroll
    for (int i = 0; i < 32; i += 8)
        t[ty + i][tx] = W[(size_t)(kb + ty + i) * N + nb + tx];
    __syncthreads();
#pragma unroll
    for (int i = 0; i < 32; i += 8) {
        float v = t[tx][ty + i];
        T[(size_t)(nb + ty + i) * K + kb + tx] = __float2half_rn(v);
    }
}

// ---------------------------------------------------------------------------
// LayerNorm -> fp16
// ---------------------------------------------------------------------------
__global__ void ln_kernel(const float* __restrict__ X,
                          const float* __restrict__ gam,
                          const float* __restrict__ bet,
                          __half* __restrict__ Y)
{
    __shared__ float red[8];
    int t = blockIdx.x;
    int tid = threadIdx.x;
    const float* x = X + (size_t)t * DIM;

    float4 v = *(const float4*)(x + tid * 4);
    float s  = v.x + v.y + v.z + v.w;
    float s2 = fmaf(v.x, v.x, fmaf(v.y, v.y, fmaf(v.z, v.z, v.w * v.w)));
#pragma unroll
    for (int o = 16; o > 0; o >>= 1) {
        s  += __shfl_xor_sync(0xffffffffu, s,  o);
        s2 += __shfl_xor_sync(0xffffffffu, s2, o);
    }
    int w = tid >> 5;
    if ((tid & 31) == 0) { red[w] = s; red[4 + w] = s2; }
    __syncthreads();
    s  = red[0] + red[1] + red[2] + red[3];
    s2 = red[4] + red[5] + red[6] + red[7];
    float mean = s * (1.0f / DIM);
    float var  = s2 * (1.0f / DIM) - mean * mean;
    float rstd = rsqrtf(var + 1e-5f);

    float4 gg = *(const float4*)(gam + tid * 4);
    float4 bb = *(const float4*)(bet + tid * 4);
    float o0 = (v.x - mean) * rstd * gg.x + bb.x;
    float o1 = (v.y - mean) * rstd * gg.y + bb.y;
    float o2 = (v.z - mean) * rstd * gg.z + bb.z;
    float o3 = (v.w - mean) * rstd * gg.w + bb.w;

    uint2 u = make_uint2(pack_h2(o0, o1), pack_h2(o2, o3));
    *(uint2*)(Y + (size_t)t * DIM + tid * 4) = u;
}

// ---------------------------------------------------------------------------
// mma.sync GEMM: C[M,N] = epi(A[M,K] @ B[N,K]^T + bias)
// Tile 128x128x32, 8 warps (4x2, each 32x64), 3-stage cp.async, fp16.
// EPI: 0 = bias->fp32   1 = bias+gelu->fp16   2 = bias+res->fp32
// smem per stage: A 8K | B 8K = 16KB.  3 stages + 512B bias.
// Swizzle: 16B seg s of row r stored at seg (s ^ ((r>>1)&3)).
// ---------------------------------------------------------------------------
#define MG_STAGE 16384
#define MG_SMEM  (3 * MG_STAGE + 512)

__device__ __forceinline__ void mg_load_chunk(
    uint32_t st,
    const __half* __restrict__ A, const __half* __restrict__ B,
    int bm, int bn, int K, int k0, int tid)
{
#pragma unroll
    for (int i = 0; i < 2; i++) {
        int ch = tid + (i << 8);
        int r  = ch >> 2;
        int s  = ch & 3;
        uint32_t off = (uint32_t)(r * 64) + (uint32_t)((s ^ ((r >> 1) & 3)) << 4);
        cpa16(st + off,        A + (size_t)(bm + r) * K + k0 + s * 8);
        cpa16(st + 8192 + off, B + (size_t)(bn + r) * K + k0 + s * 8);
    }
}

template<int EPI>
__global__ __launch_bounds__(256, 2)
void mg_gemm(const __half* __restrict__ A, const __half* __restrict__ B,
             const float* __restrict__ bias, const float* __restrict__ res,
             float* __restrict__ outF, __half* __restrict__ outH,
             int M, int N, int K)
{
    extern __shared__ __align__(1024) char smem[];
    const int tid  = threadIdx.x;
    const int lane = tid & 31;
    const int wid  = tid >> 5;
    const int wm   = wid & 3;          // m offset 32*wm
    const int wn   = wid >> 2;         // n offset 64*wn
    const int bm = blockIdx.y * 128, bn = blockIdx.x * 128;

    float* sbias = (float*)(smem + 3 * MG_STAGE);
    if (tid < 32)
        ((float4*)sbias)[tid] = ((const float4*)(bias + bn))[tid];

    uint32_t sb = smem_u32(smem);

    float acc[2][8][4];
#pragma unroll
    for (int mi = 0; mi < 2; mi++)
#pragma unroll
        for (int ni = 0; ni < 8; ni++)
#pragma unroll
            for (int j = 0; j < 4; j++) acc[mi][ni][j] = 0.0f;

    const int nch = K >> 5;

    mg_load_chunk(sb, A, B, bm, bn, K, 0, tid);
    asm volatile("cp.async.commit_group;");
    if (nch > 1)
        mg_load_chunk(sb + MG_STAGE, A, B, bm, bn, K, 32, tid);
    asm volatile("cp.async.commit_group;");

    const int j8 = lane & 7;
    const int a_row_off = wm * 32 + j8 + ((lane >> 3) & 1) * 8;
    const int a_seg_off = (lane >> 4);
    const int b_row_off = wn * 64 + j8 + ((lane >> 4) & 1) * 8;
    const int b_seg_off = ((lane >> 3) & 1);

    for (int c = 0; c < nch; c++) {
        asm volatile("cp.async.wait_group 1;");
        __syncthreads();

        if (c + 2 < nch)
            mg_load_chunk(sb + (uint32_t)((c + 2) % 3) * MG_STAGE,
                          A, B, bm, bn, K, (c + 2) << 5, tid);
        asm volatile("cp.async.commit_group;");

        uint32_t st = sb + (uint32_t)(c % 3) * MG_STAGE;

#pragma unroll
        for (int kk = 0; kk < 2; kk++) {
            uint32_t a_f[2][4];
#pragma unroll
            for (int mi = 0; mi < 2; mi++) {
                int row = a_row_off + mi * 16;
                int seg = kk * 2 + a_seg_off;
                uint32_t off = (uint32_t)(row * 64) +
                               (uint32_t)((seg ^ ((row >> 1) & 3)) << 4);
                ldsm_x4(a_f[mi], st + off);
            }
            uint32_t b_f[4][4];
#pragma unroll
            for (int pi = 0; pi < 4; pi++) {
                int row = b_row_off + pi * 16;
                int seg = kk * 2 + b_seg_off;
                uint32_t off = (uint32_t)(row * 64) +
                               (uint32_t)((seg ^ ((row >> 1) & 3)) << 4);
                ldsm_x4(b_f[pi], st + 8192 + off);
            }
#pragma unroll
            for (int mi = 0; mi < 2; mi++)
#pragma unroll
                for (int ni = 0; ni < 8; ni++)
                    mma16816(acc[mi][ni], a_f[mi], &b_f[ni >> 1][(ni & 1) * 2]);
        }
    }
    __syncthreads();

    // Epilogue: regs {r0,r1} row base+lane/4, {r2,r3} row +8,
    // cols = wn*64 + ni*8 + 2*(lane&3) + {0,1}
#pragma unroll
    for (int mi = 0; mi < 2; mi++) {
        int r0 = bm + wm * 32 + mi * 16 + (lane >> 2);
#pragma unroll
        for (int ni = 0; ni < 8; ni++) {
            int cb = wn * 64 + ni * 8 + 2 * (lane & 3);
            float bv0 = sbias[cb], bv1 = sbias[cb + 1];
            float v0 = acc[mi][ni][0] + bv0;
            float v1 = acc[mi][ni][1] + bv1;
            float v2 = acc[mi][ni][2] + bv0;
            float v3 = acc[mi][ni][3] + bv1;
            size_t g0 = (size_t)r0 * N + bn + cb;
            size_t g1 = (size_t)(r0 + 8) * N + bn + cb;
            if (EPI == 0) {
                *(float2*)(outF + g0) = make_float2(v0, v1);
                *(float2*)(outF + g1) = make_float2(v2, v3);
            } else if (EPI == 2) {
                float2 q0 = *(const float2*)(res + g0);
                float2 q1 = *(const float2*)(res + g1);
                *(float2*)(outF + g0) = make_float2(v0 + q0.x, v1 + q0.y);
                *(float2*)(outF + g1) = make_float2(v2 + q1.x, v3 + q1.y);
            } else {
                v0 = gelu_tanh(v0); v1 = gelu_tanh(v1);
                v2 = gelu_tanh(v2); v3 = gelu_tanh(v3);
                *(uint32_t*)(outH + g0) = pack_h2(v0, v1);
                *(uint32_t*)(outH + g1) = pack_h2(v2, v3);
            }
        }
    }
}

// ---------------------------------------------------------------------------
// Windowed attention (fp32 in, fp16 out)
// ---------------------------------------------------------------------------
__global__ __launch_bounds__(256)
void attn_kernel(const float* __restrict__ Q,
                 const float* __restrict__ KV,
                 const int*   __restrict__ relIdx,
                 const float* __restrict__ table,
                 __half* __restrict__ O)
{
    __shared__ float sQ[64][33];
    __shared__ float sK[64][33];
    __shared__ float sV[64][32];
    __shared__ float sA[64][65];
    __shared__ int   sTok[64];
    __shared__ int   sLab[64];
    __shared__ float sTab[225];

    int h   = blockIdx.x;
    int win = blockIdx.y;
    int b   = blockIdx.z;
    int nwh = win >> 3, nww = win & 7;
    int tid = threadIdx.x;

    if (tid < 64) {
        int i = tid >> 3, j = tid & 7;
        int gh = (nwh * WSZ + i + SHF) & (HH - 1);
        int gw = (nww * WSZ + j + SHF) & (WW - 1);
        sTok[tid] = ((b * HH + gh) << 6) + gw;
        int ih = nwh * WSZ + i, iw = nww * WSZ + j;
        int rh = (ih >= HH - WSZ) + (ih >= HH - SHF);
        int rw = (iw >= WW - WSZ) + (iw >= WW - SHF);
        sLab[tid] = rh * 3 + rw;
    }
    if (tid < 225) sTab[tid] = table[tid * NHEAD + h];
    __syncthreads();

    for (int idx = tid; idx < 64 * 8; idx += 256) {
        int row = idx >> 3;
        int c4  = (idx & 7) << 2;
        size_t qb = (size_t)sTok[row] * DIM + h * DKH + c4;
        float4 qv = *(const float4*)(Q + qb);
        sQ[row][c4 + 0] = qv.x; sQ[row][c4 + 1] = qv.y;
        sQ[row][c4 + 2] = qv.z; sQ[row][c4 + 3] = qv.w;
        size_t kb = (size_t)sTok[row] * (2 * DIM) + h * DKH + c4;
        float4 kvv = *(const float4*)(KV + kb);
        sK[row][c4 + 0] = kvv.x; sK[row][c4 + 1] = kvv.y;
        sK[row][c4 + 2] = kvv.z; sK[row][c4 + 3] = kvv.w;
        float4 vv = *(const float4*)(KV + kb + DIM);
        *(float4*)&sV[row][c4] = vv;
    }
    __syncthreads();

    {
        int r = tid >> 2;
        int qd = tid & 3;
        float qreg[DKH];
#pragma unroll
        for (int d = 0; d < DKH; d++) qreg[d] = sQ[r][d];

        float sc[16];
        int labr = sLab[r];
        const int* ri = relIdx + r * 64;
#pragma unroll
        for (int c = 0; c < 16; c++) {
            int col = qd + (c << 2);
            float a = 0.0f;
#pragma unroll
            for (int d = 0; d < DKH; d++)
                a = fmaf(qreg[d], sK[col][d], a);
            a = a * SCALE + sTab[ri[col]];
            if (labr != sLab[col]) a = -1e9f;
            sc[c] = a;
        }
        float mx = sc[0];
#pragma unroll
        for (int c = 1; c < 16; c++) mx = fmaxf(mx, sc[c]);
        mx = fmaxf(mx, __shfl_xor_sync(0xffffffffu, mx, 1));
        mx = fmaxf(mx, __shfl_xor_sync(0xffffffffu, mx, 2));
        float sum = 0.0f;
#pragma unroll
        for (int c = 0; c < 16; c++) { sc[c] = __expf(sc[c] - mx); sum += sc[c]; }
        sum += __shfl_xor_sync(0xffffffffu, sum, 1);
        sum += __shfl_xor_sync(0xffffffffu, sum, 2);
        float inv = 1.0f / sum;
#pragma unroll
        for (int c = 0; c < 16; c++) sA[r][qd + (c << 2)] = sc[c] * inv;
    }
    __syncthreads();

    {
        int row = tid >> 2;
        int d0  = (tid & 3) << 3;
        float a8[8];
#pragma unroll
        for (int i = 0; i < 8; i++) a8[i] = 0.0f;
#pragma unroll
        for (int k = 0; k < 64; k++) {
            float a = sA[row][k];
            float4 v0 = *(float4*)&sV[k][d0];
            float4 v1 = *(float4*)&sV[k][d0 + 4];
            a8[0] = fmaf(a, v0.x, a8[0]);
            a8[1] = fmaf(a, v0.y, a8[1]);
            a8[2] = fmaf(a, v0.z, a8[2]);
            a8[3] = fmaf(a, v0.w, a8[3]);
            a8[4] = fmaf(a, v1.x, a8[4]);
            a8[5] = fmaf(a, v1.y, a8[5]);
            a8[6] = fmaf(a, v1.z, a8[6]);
            a8[7] = fmaf(a, v1.w, a8[7]);
        }
        size_t base = (size_t)sTok[row] * DIM + h * DKH + d0;
        *(uint2*)(O + base)     = make_uint2(pack_h2(a8[0], a8[1]), pack_h2(a8[2], a8[3]));
        *(uint2*)(O + base + 4) = make_uint2(pack_h2(a8[4], a8[5]), pack_h2(a8[6], a8[7]));
    }
}

// ---------------------------------------------------------------------------
// Launch
// ---------------------------------------------------------------------------
extern "C" void kernel_launch(void* const* d_in, const int* in_sizes, int n_in,
                              void* d_out, int out_size)
{
    const float* x_in      = (const float*)d_in[0];
    const int*   rel_index = (const int*)  d_in[2];
    const float* Wq        = (const float*)d_in[3];
    const float* bq        = (const float*)d_in[4];
    const float* Wkv       = (const float*)d_in[5];
    const float* bkv       = (const float*)d_in[6];
    const float* Wo        = (const float*)d_in[7];
    const float* bo        = (const float*)d_in[8];
    const float* rel_table = (const float*)d_in[9];
    const float* ln1_g     = (const float*)d_in[10];
    const float* ln1_b     = (const float*)d_in[11];
    const float* ln2_g     = (const float*)d_in[12];
    const float* ln2_b     = (const float*)d_in[13];
    const float* W1        = (const float*)d_in[14];
    const float* b1        = (const float*)d_in[15];
    const float* W2        = (const float*)d_in[16];
    const float* b2        = (const float*)d_in[17];

    float* xbuf = (float*)d_out;

    __half *xn, *o, *m, *wt;
    float *q, *kv;
    cudaGetSymbolAddress((void**)&xn, g_xn);
    cudaGetSymbolAddress((void**)&q,  g_q);
    cudaGetSymbolAddress((void**)&kv, g_kv);
    cudaGetSymbolAddress((void**)&o,  g_o);
    cudaGetSymbolAddress((void**)&m,  g_m);
    cudaGetSymbolAddress((void**)&wt, g_wt);

    cudaFuncSetAttribute(mg_gemm<0>, cudaFuncAttributeMaxDynamicSharedMemorySize, MG_SMEM);
    cudaFuncSetAttribute(mg_gemm<1>, cudaFuncAttributeMaxDynamicSharedMemorySize, MG_SMEM);
    cudaFuncSetAttribute(mg_gemm<2>, cudaFuncAttributeMaxDynamicSharedMemorySize, MG_SMEM);

    cudaMemcpyAsync(xbuf, x_in, (size_t)NTOK * DIM * sizeof(float),
                    cudaMemcpyDeviceToDevice);

    // Weight transform (all layers)
    for (int l = 0; l < NLAYER; l++) {
        size_t lw = (size_t)l * WLAYER;
        wtrans_kernel<<<dim3(512/32, 512/32), 256>>>(
            Wq + (size_t)l*DIM*DIM, wt + lw + WOFF_Q, 512, 512);
        wtrans_kernel<<<dim3(1024/32, 512/32), 256>>>(
            Wkv + (size_t)l*DIM*2*DIM, wt + lw + WOFF_KV, 512, 1024);
        wtrans_kernel<<<dim3(512/32, 512/32), 256>>>(
            Wo + (size_t)l*DIM*DIM, wt + lw + WOFF_O, 512, 512);
        wtrans_kernel<<<dim3(2048/32, 512/32), 256>>>(
            W1 + (size_t)l*DIM*4*DIM, wt + lw + WOFF_W1, 512, 2048);
        wtrans_kernel<<<dim3(512/32, 2048/32), 256>>>(
            W2 + (size_t)l*4*DIM*DIM, wt + lw + WOFF_W2, 2048, 512);
    }

    dim3 gLN(NTOK), bLN(128);
    dim3 gAttn(NHEAD, 64, BATCH), bAttn(256);

    for (int l = 0; l < NLAYER; l++) {
        size_t lw = (size_t)l * WLAYER;
        const float* bqv  = bq  + (size_t)l * DIM;
        const float* bkvv = bkv + (size_t)l * 2 * DIM;
        const float* bov  = bo  + (size_t)l * DIM;
        const float* tab  = rel_table + (size_t)l * 225 * NHEAD;
        const float* b1v  = b1  + (size_t)l * 4 * DIM;
        const float* b2v  = b2  + (size_t)l * DIM;

        ln_kernel<<<gLN, bLN>>>(xbuf, ln1_g + (size_t)l*DIM, ln1_b + (size_t)l*DIM, xn);
        mg_gemm<0><<<dim3(4, 256), 256, MG_SMEM>>>(
            xn, wt + lw + WOFF_Q, bqv, nullptr, q, nullptr, NTOK, 512, 512);
        mg_gemm<0><<<dim3(8, 256), 256, MG_SMEM>>>(
            xn, wt + lw + WOFF_KV, bkvv, nullptr, kv, nullptr, NTOK, 1024, 512);
        attn_kernel<<<gAttn, bAttn>>>(q, kv, rel_index, tab, o);
        mg_gemm<2><<<dim3(4, 256), 256, MG_SMEM>>>(
            o, wt + lw + WOFF_O, bov, xbuf, xbuf, nullptr, NTOK, 512, 512);
        ln_kernel<<<gLN, bLN>>>(xbuf, ln2_g + (size_t)l*DIM, ln2_b + (size_t)l*DIM, xn);
        mg_gemm<1><<<dim3(16, 256), 256, MG_SMEM>>>(
            xn, wt + lw + WOFF_W1, b1v, nullptr, nullptr, m, NTOK, 2048, 512);
        mg_gemm<2><<<dim3(4, 256), 256, MG_SMEM>>>(
            m, wt + lw + WOFF_W2, b2v, xbuf, xbuf, nullptr, NTOK, 512, 2048);
    }
}

// round 7
// speedup vs baseline: 5.9504x; 1.1903x over previous
#include <cuda_runtime.h>
#include <cuda_fp16.h>
#include <math.h>
#include <stdint.h>

// ---------------------------------------------------------------------------
// Swin-style transformer encoder. mma.sync fp16 GEMMs + half2 attention.
// B=8, H=W=64, D=512, NH=16, DK=32, WS=8, SH=4, L=4
// ---------------------------------------------------------------------------

#define BATCH 8
#define HH 64
#define WW 64
#define DIM 512
#define NHEAD 16
#define DKH 32
#define WSZ 8
#define SHF 4
#define NLAYER 4
#define NTOK (BATCH * HH * WW)          // 32768
#define SCALE 0.17677669529663687f     // 1/sqrt(32)

#define WOFF_Q  0
#define WOFF_KV 262144
#define WOFF_O  786432
#define WOFF_W1 1048576
#define WOFF_W2 2097152
#define WLAYER  3145728

// ---------------------------------------------------------------------------
// Scratch
// ---------------------------------------------------------------------------
__device__ __half g_xn [(size_t)NTOK * DIM];
__device__ __half g_q  [(size_t)NTOK * DIM];
__device__ __half g_kv [(size_t)NTOK * DIM * 2];
__device__ __half g_o  [(size_t)NTOK * DIM];
__device__ __half g_m  [(size_t)NTOK * DIM * 4];
__device__ __half g_wt [(size_t)NLAYER * WLAYER];

// ---------------------------------------------------------------------------
// Helpers
// ---------------------------------------------------------------------------
__device__ __forceinline__ uint32_t smem_u32(const void* p) {
    uint32_t a;
    asm("{ .reg .u64 t; cvta.to.shared.u64 t, %1; cvt.u32.u64 %0, t; }"
        : "=r"(a) : "l"(p));
    return a;
}
__device__ __forceinline__ void cpa16(uint32_t dst, const void* src) {
    asm volatile("cp.async.cg.shared.global [%0], [%1], 16;" :: "r"(dst), "l"(src));
}
__device__ __forceinline__ void ldsm_x4(uint32_t* r, uint32_t addr) {
    asm volatile("ldmatrix.sync.aligned.m8n8.x4.shared.b16 {%0,%1,%2,%3}, [%4];"
                 : "=r"(r[0]), "=r"(r[1]), "=r"(r[2]), "=r"(r[3]) : "r"(addr));
}
__device__ __forceinline__ void mma16816(float* d, const uint32_t* a, const uint32_t* b) {
    asm volatile("mma.sync.aligned.m16n8k16.row.col.f32.f16.f16.f32 "
        "{%0,%1,%2,%3}, {%4,%5,%6,%7}, {%8,%9}, {%0,%1,%2,%3};"
        : "+f"(d[0]), "+f"(d[1]), "+f"(d[2]), "+f"(d[3])
        : "r"(a[0]), "r"(a[1]), "r"(a[2]), "r"(a[3]), "r"(b[0]), "r"(b[1]));
}
__device__ __forceinline__ float gelu_tanh(float u) {
    float t = tanhf(0.7978845608028654f * (u + 0.044715f * u * u * u));
    return 0.5f * u * (1.0f + t);
}
__device__ __forceinline__ uint32_t pack_h2(float a, float b) {
    __half2 h = __floats2half2_rn(a, b);
    return *(uint32_t*)&h;
}

// ---------------------------------------------------------------------------
// Weight transform: W[K,N] fp32 -> Wt[N,K] fp16  (blockIdx.z = layer)
// ---------------------------------------------------------------------------
__global__ void wtrans_kernel(const float* __restrict__ W,
                              __half* __restrict__ T,
                              int K, int N)
{
    W += (size_t)blockIdx.z * K * N;
    T += (size_t)blockIdx.z * WLAYER;
    __shared__ float t[32][33];
    int nb = blockIdx.x * 32, kb = blockIdx.y * 32;
    int tx = threadIdx.x & 31, ty = threadIdx.x >> 5;
#pragma unroll
    for (int i = 0; i < 32; i += 8)
        t[ty + i][tx] = W[(size_t)(kb + ty + i) * N + nb + tx];
    __syncthreads();
#pragma unroll
    for (int i = 0; i < 32; i += 8)
        T[(size_t)(nb + ty + i) * K + kb + tx] = __float2half_rn(t[tx][ty + i]);
}

// ---------------------------------------------------------------------------
// LayerNorm: warp per token (8 tokens / 256-thread block)
// ---------------------------------------------------------------------------
__global__ __launch_bounds__(256)
void ln_kernel(const float* __restrict__ X,
               const float* __restrict__ gam,
               const float* __restrict__ bet,
               __half* __restrict__ Y)
{
    int t  = blockIdx.x * 8 + (threadIdx.x >> 5);
    int ln = threadIdx.x & 31;
    const float4* xr = (const float4*)(X + (size_t)t * DIM);

    float4 v[4];
    float s = 0.0f, s2 = 0.0f;
#pragma unroll
    for (int j = 0; j < 4; j++) {
        v[j] = xr[ln + 32 * j];
        s  += v[j].x + v[j].y + v[j].z + v[j].w;
        s2 += fmaf(v[j].x, v[j].x, fmaf(v[j].y, v[j].y,
              fmaf(v[j].z, v[j].z, v[j].w * v[j].w)));
    }
#pragma unroll
    for (int o = 16; o > 0; o >>= 1) {
        s  += __shfl_xor_sync(0xffffffffu, s,  o);
        s2 += __shfl_xor_sync(0xffffffffu, s2, o);
    }
    float mean = s * (1.0f / DIM);
    float var  = s2 * (1.0f / DIM) - mean * mean;
    float rstd = rsqrtf(var + 1e-5f);

    uint2* yr = (uint2*)(Y + (size_t)t * DIM);
#pragma unroll
    for (int j = 0; j < 4; j++) {
        float4 g4 = ((const float4*)gam)[ln + 32 * j];
        float4 b4 = ((const float4*)bet)[ln + 32 * j];
        float o0 = (v[j].x - mean) * rstd * g4.x + b4.x;
        float o1 = (v[j].y - mean) * rstd * g4.y + b4.y;
        float o2 = (v[j].z - mean) * rstd * g4.z + b4.z;
        float o3 = (v[j].w - mean) * rstd * g4.w + b4.w;
        yr[ln + 32 * j] = make_uint2(pack_h2(o0, o1), pack_h2(o2, o3));
    }
}

// ---------------------------------------------------------------------------
// mma.sync GEMM: C[M,N] = epi(A[M,K] @ B[N,K]^T + bias)
// Tile 128x128x32, 8 warps (4x2), 3-stage cp.async, fp16.
// EPI: 1 = bias+gelu->fp16   2 = bias+res->fp32   3 = bias->fp16
// ---------------------------------------------------------------------------
#define MG_STAGE 16384
#define MG_SMEM  (3 * MG_STAGE + 512)

__device__ __forceinline__ void mg_load_chunk(
    uint32_t st,
    const __half* __restrict__ A, const __half* __restrict__ B,
    int bm, int bn, int K, int k0, int tid)
{
#pragma unroll
    for (int i = 0; i < 2; i++) {
        int ch = tid + (i << 8);
        int r  = ch >> 2;
        int s  = ch & 3;
        uint32_t off = (uint32_t)(r * 64) + (uint32_t)((s ^ ((r >> 1) & 3)) << 4);
        cpa16(st + off,        A + (size_t)(bm + r) * K + k0 + s * 8);
        cpa16(st + 8192 + off, B + (size_t)(bn + r) * K + k0 + s * 8);
    }
}

template<int EPI>
__global__ __launch_bounds__(256, 2)
void mg_gemm(const __half* __restrict__ A, const __half* __restrict__ B,
             const float* __restrict__ bias, const float* __restrict__ res,
             float* __restrict__ outF, __half* __restrict__ outH,
             int M, int N, int K)
{
    extern __shared__ __align__(1024) char smem[];
    const int tid  = threadIdx.x;
    const int lane = tid & 31;
    const int wid  = tid >> 5;
    const int wm   = wid & 3;
    const int wn   = wid >> 2;
    const int bm = blockIdx.y * 128, bn = blockIdx.x * 128;

    float* sbias = (float*)(smem + 3 * MG_STAGE);
    if (tid < 32)
        ((float4*)sbias)[tid] = ((const float4*)(bias + bn))[tid];

    uint32_t sb = smem_u32(smem);

    float acc[2][8][4];
#pragma unroll
    for (int mi = 0; mi < 2; mi++)
#pragma unroll
        for (int ni = 0; ni < 8; ni++)
#pragma unroll
            for (int j = 0; j < 4; j++) acc[mi][ni][j] = 0.0f;

    const int nch = K >> 5;

    mg_load_chunk(sb, A, B, bm, bn, K, 0, tid);
    asm volatile("cp.async.commit_group;");
    if (nch > 1)
        mg_load_chunk(sb + MG_STAGE, A, B, bm, bn, K, 32, tid);
    asm volatile("cp.async.commit_group;");

    const int j8 = lane & 7;
    const int a_row_off = wm * 32 + j8 + ((lane >> 3) & 1) * 8;
    const int a_seg_off = (lane >> 4);
    const int b_row_off = wn * 64 + j8 + ((lane >> 4) & 1) * 8;
    const int b_seg_off = ((lane >> 3) & 1);

    for (int c = 0; c < nch; c++) {
        asm volatile("cp.async.wait_group 1;");
        __syncthreads();

        if (c + 2 < nch)
            mg_load_chunk(sb + (uint32_t)((c + 2) % 3) * MG_STAGE,
                          A, B, bm, bn, K, (c + 2) << 5, tid);
        asm volatile("cp.async.commit_group;");

        uint32_t st = sb + (uint32_t)(c % 3) * MG_STAGE;

#pragma unroll
        for (int kk = 0; kk < 2; kk++) {
            uint32_t a_f[2][4];
#pragma unroll
            for (int mi = 0; mi < 2; mi++) {
                int row = a_row_off + mi * 16;
                int seg = kk * 2 + a_seg_off;
                uint32_t off = (uint32_t)(row * 64) +
                               (uint32_t)((seg ^ ((row >> 1) & 3)) << 4);
                ldsm_x4(a_f[mi], st + off);
            }
            uint32_t b_f[4][4];
#pragma unroll
            for (int pi = 0; pi < 4; pi++) {
                int row = b_row_off + pi * 16;
                int seg = kk * 2 + b_seg_off;
                uint32_t off = (uint32_t)(row * 64) +
                               (uint32_t)((seg ^ ((row >> 1) & 3)) << 4);
                ldsm_x4(b_f[pi], st + 8192 + off);
            }
#pragma unroll
            for (int mi = 0; mi < 2; mi++)
#pragma unroll
                for (int ni = 0; ni < 8; ni++)
                    mma16816(acc[mi][ni], a_f[mi], &b_f[ni >> 1][(ni & 1) * 2]);
        }
    }
    __syncthreads();

#pragma unroll
    for (int mi = 0; mi < 2; mi++) {
        int r0 = bm + wm * 32 + mi * 16 + (lane >> 2);
#pragma unroll
        for (int ni = 0; ni < 8; ni++) {
            int cb = wn * 64 + ni * 8 + 2 * (lane & 3);
            float bv0 = sbias[cb], bv1 = sbias[cb + 1];
            float v0 = acc[mi][ni][0] + bv0;
            float v1 = acc[mi][ni][1] + bv1;
            float v2 = acc[mi][ni][2] + bv0;
            float v3 = acc[mi][ni][3] + bv1;
            size_t g0 = (size_t)r0 * N + bn + cb;
            size_t g1 = (size_t)(r0 + 8) * N + bn + cb;
            if (EPI == 2) {
                float2 q0 = *(const float2*)(res + g0);
                float2 q1 = *(const float2*)(res + g1);
                *(float2*)(outF + g0) = make_float2(v0 + q0.x, v1 + q0.y);
                *(float2*)(outF + g1) = make_float2(v2 + q1.x, v3 + q1.y);
            } else if (EPI == 3) {
                *(uint32_t*)(outH + g0) = pack_h2(v0, v1);
                *(uint32_t*)(outH + g1) = pack_h2(v2, v3);
            } else {
                v0 = gelu_tanh(v0); v1 = gelu_tanh(v1);
                v2 = gelu_tanh(v2); v3 = gelu_tanh(v3);
                *(uint32_t*)(outH + g0) = pack_h2(v0, v1);
                *(uint32_t*)(outH + g1) = pack_h2(v2, v3);
            }
        }
    }
}

// ---------------------------------------------------------------------------
// Windowed attention (fp16 in, fp16 out). 2-row register tiling + half2 smem.
// Thread t: rows {t>>3, (t>>3)+32}, cols {(t&7)+8c | c=0..7}.
// ---------------------------------------------------------------------------
__global__ __launch_bounds__(256)
void attn_kernel(const __half* __restrict__ Q,
                 const __half* __restrict__ KV,
                 const int*   __restrict__ relIdx,
                 const float* __restrict__ table,
                 __half* __restrict__ O)
{
    __shared__ __half2 sQ[64][20];
    __shared__ __half2 sK[64][20];
    __shared__ __half2 sV[64][20];
    __shared__ float   sA[64][65];
    __shared__ int     sTok[64];
    __shared__ int     sLab[64];
    __shared__ float   sTab[225];

    int h   = blockIdx.x;
    int win = blockIdx.y;
    int b   = blockIdx.z;
    int nwh = win >> 3, nww = win & 7;
    int tid = threadIdx.x;

    if (tid < 64) {
        int i = tid >> 3, j = tid & 7;
        int gh = (nwh * WSZ + i + SHF) & (HH - 1);
        int gw = (nww * WSZ + j + SHF) & (WW - 1);
        sTok[tid] = ((b * HH + gh) << 6) + gw;
        int ih = nwh * WSZ + i, iw = nww * WSZ + j;
        int rh = (ih >= HH - WSZ) + (ih >= HH - SHF);
        int rw = (iw >= WW - WSZ) + (iw >= WW - SHF);
        sLab[tid] = rh * 3 + rw;
    }
    if (tid < 225) sTab[tid] = table[tid * NHEAD + h];
    __syncthreads();

    {
        int r  = tid >> 2;
        int sg = tid & 3;
        size_t qoff = (size_t)sTok[r] * DIM + h * DKH + sg * 8;
        *(uint4*)&sQ[r][sg * 4] = *(const uint4*)(Q + qoff);
        size_t koff = (size_t)sTok[r] * (2 * DIM) + h * DKH + sg * 8;
        *(uint4*)&sK[r][sg * 4] = *(const uint4*)(KV + koff);
        *(uint4*)&sV[r][sg * 4] = *(const uint4*)(KV + koff + DIM);
    }
    __syncthreads();

    const int r0 = tid >> 3;
    const int cl = tid & 7;

    {
        float2 q0[16], q1[16];
#pragma unroll
        for (int d = 0; d < 16; d++) {
            q0[d] = __half22float2(sQ[r0][d]);
            q1[d] = __half22float2(sQ[r0 + 32][d]);
        }
        int lab0 = sLab[r0], lab1 = sLab[r0 + 32];
        float sc0[8], sc1[8];
#pragma unroll
        for (int c = 0; c < 8; c++) {
            int col = cl + (c << 3);
            float a0 = 0.0f, a1 = 0.0f;
#pragma unroll
            for (int d = 0; d < 16; d++) {
                float2 k2 = __half22float2(sK[col][d]);
                a0 = fmaf(q0[d].x, k2.x, a0);
                a0 = fmaf(q0[d].y, k2.y, a0);
                a1 = fmaf(q1[d].x, k2.x, a1);
                a1 = fmaf(q1[d].y, k2.y, a1);
            }
            int lc = sLab[col];
            float bi0 = sTab[relIdx[r0 * 64 + col]];
            float bi1 = sTab[relIdx[(r0 + 32) * 64 + col]];
            a0 = a0 * SCALE + bi0;
            a1 = a1 * SCALE + bi1;
            if (lab0 != lc) a0 = -1e9f;
            if (lab1 != lc) a1 = -1e9f;
            sc0[c] = a0; sc1[c] = a1;
        }
        float m0 = sc0[0], m1 = sc1[0];
#pragma unroll
        for (int c = 1; c < 8; c++) { m0 = fmaxf(m0, sc0[c]); m1 = fmaxf(m1, sc1[c]); }
#pragma unroll
        for (int o = 1; o < 8; o <<= 1) {
            m0 = fmaxf(m0, __shfl_xor_sync(0xffffffffu, m0, o));
            m1 = fmaxf(m1, __shfl_xor_sync(0xffffffffu, m1, o));
        }
        float s0 = 0.0f, s1 = 0.0f;
#pragma unroll
        for (int c = 0; c < 8; c++) {
            sc0[c] = __expf(sc0[c] - m0); s0 += sc0[c];
            sc1[c] = __expf(sc1[c] - m1); s1 += sc1[c];
        }
#pragma unroll
        for (int o = 1; o < 8; o <<= 1) {
            s0 += __shfl_xor_sync(0xffffffffu, s0, o);
            s1 += __shfl_xor_sync(0xffffffffu, s1, o);
        }
        float i0 = 1.0f / s0, i1 = 1.0f / s1;
#pragma unroll
        for (int c = 0; c < 8; c++) {
            int col = cl + (c << 3);
            sA[r0][col]      = sc0[c] * i0;
            sA[r0 + 32][col] = sc1[c] * i1;
        }
    }
    __syncthreads();

    {
        const int dh = (tid & 7) * 2;          // half2 pair index -> dims dh*2..+3
        float o00 = 0, o01 = 0, o02 = 0, o03 = 0;
        float o10 = 0, o11 = 0, o12 = 0, o13 = 0;
#pragma unroll
        for (int k = 0; k < 64; k++) {
            float a0 = sA[r0][k];
            float a1 = sA[r0 + 32][k];
            uint2 vv = *(uint2*)&sV[k][dh];
            float2 v0 = __half22float2(*(__half2*)&vv.x);
            float2 v1 = __half22float2(*(__half2*)&vv.y);
            o00 = fmaf(a0, v0.x, o00); o01 = fmaf(a0, v0.y, o01);
            o02 = fmaf(a0, v1.x, o02); o03 = fmaf(a0, v1.y, o03);
            o10 = fmaf(a1, v0.x, o10); o11 = fmaf(a1, v0.y, o11);
            o12 = fmaf(a1, v1.x, o12); o13 = fmaf(a1, v1.y, o13);
        }
        size_t b0 = (size_t)sTok[r0] * DIM + h * DKH + dh * 2;
        *(uint2*)(O + b0) = make_uint2(pack_h2(o00, o01), pack_h2(o02, o03));
        size_t b1 = (size_t)sTok[r0 + 32] * DIM + h * DKH + dh * 2;
        *(uint2*)(O + b1) = make_uint2(pack_h2(o10, o11), pack_h2(o12, o13));
    }
}

// ---------------------------------------------------------------------------
// Launch
// ---------------------------------------------------------------------------
extern "C" void kernel_launch(void* const* d_in, const int* in_sizes, int n_in,
                              void* d_out, int out_size)
{
    const float* x_in      = (const float*)d_in[0];
    const int*   rel_index = (const int*)  d_in[2];
    const float* Wq        = (const float*)d_in[3];
    const float* bq        = (const float*)d_in[4];
    const float* Wkv       = (const float*)d_in[5];
    const float* bkv       = (const float*)d_in[6];
    const float* Wo        = (const float*)d_in[7];
    const float* bo        = (const float*)d_in[8];
    const float* rel_table = (const float*)d_in[9];
    const float* ln1_g     = (const float*)d_in[10];
    const float* ln1_b     = (const float*)d_in[11];
    const float* ln2_g     = (const float*)d_in[12];
    const float* ln2_b     = (const float*)d_in[13];
    const float* W1        = (const float*)d_in[14];
    const float* b1        = (const float*)d_in[15];
    const float* W2        = (const float*)d_in[16];
    const float* b2        = (const float*)d_in[17];

    float* xbuf = (float*)d_out;

    __half *xn, *q, *kv, *o, *m, *wt;
    cudaGetSymbolAddress((void**)&xn, g_xn);
    cudaGetSymbolAddress((void**)&q,  g_q);
    cudaGetSymbolAddress((void**)&kv, g_kv);
    cudaGetSymbolAddress((void**)&o,  g_o);
    cudaGetSymbolAddress((void**)&m,  g_m);
    cudaGetSymbolAddress((void**)&wt, g_wt);

    cudaFuncSetAttribute(mg_gemm<1>, cudaFuncAttributeMaxDynamicSharedMemorySize, MG_SMEM);
    cudaFuncSetAttribute(mg_gemm<2>, cudaFuncAttributeMaxDynamicSharedMemorySize, MG_SMEM);
    cudaFuncSetAttribute(mg_gemm<3>, cudaFuncAttributeMaxDynamicSharedMemorySize, MG_SMEM);

    cudaMemcpyAsync(xbuf, x_in, (size_t)NTOK * DIM * sizeof(float),
                    cudaMemcpyDeviceToDevice);

    // Weight transform, all layers batched via blockIdx.z
    wtrans_kernel<<<dim3(16, 16, NLAYER), 256>>>(Wq,  wt + WOFF_Q,  512, 512);
    wtrans_kernel<<<dim3(32, 16, NLAYER), 256>>>(Wkv, wt + WOFF_KV, 512, 1024);
    wtrans_kernel<<<dim3(16, 16, NLAYER), 256>>>(Wo,  wt + WOFF_O,  512, 512);
    wtrans_kernel<<<dim3(64, 16, NLAYER), 256>>>(W1,  wt + WOFF_W1, 512, 2048);
    wtrans_kernel<<<dim3(16, 64, NLAYER), 256>>>(W2,  wt + WOFF_W2, 2048, 512);

    dim3 gLN(NTOK / 8), bLN(256);
    dim3 gAttn(NHEAD, 64, BATCH), bAttn(256);

    for (int l = 0; l < NLAYER; l++) {
        size_t lw = (size_t)l * WLAYER;
        const float* bqv  = bq  + (size_t)l * DIM;
        const float* bkvv = bkv + (size_t)l * 2 * DIM;
        const float* bov  = bo  + (size_t)l * DIM;
        const float* tab  = rel_table + (size_t)l * 225 * NHEAD;
        const float* b1v  = b1  + (size_t)l * 4 * DIM;
        const float* b2v  = b2  + (size_t)l * DIM;

        ln_kernel<<<gLN, bLN>>>(xbuf, ln1_g + (size_t)l*DIM, ln1_b + (size_t)l*DIM, xn);
        mg_gemm<3><<<dim3(4, 256), 256, MG_SMEM>>>(
            xn, wt + lw + WOFF_Q, bqv, nullptr, nullptr, q, NTOK, 512, 512);
        mg_gemm<3><<<dim3(8, 256), 256, MG_SMEM>>>(
            xn, wt + lw + WOFF_KV, bkvv, nullptr, nullptr, kv, NTOK, 1024, 512);
        attn_kernel<<<gAttn, bAttn>>>(q, kv, rel_index, tab, o);
        mg_gemm<2><<<dim3(4, 256), 256, MG_SMEM>>>(
            o, wt + lw + WOFF_O, bov, xbuf, xbuf, nullptr, NTOK, 512, 512);
        ln_kernel<<<gLN, bLN>>>(xbuf, ln2_g + (size_t)l*DIM, ln2_b + (size_t)l*DIM, xn);
        mg_gemm<1><<<dim3(16, 256), 256, MG_SMEM>>>(
            xn, wt + lw + WOFF_W1, b1v, nullptr, nullptr, m, NTOK, 2048, 512);
        mg_gemm<2><<<dim3(4, 256), 256, MG_SMEM>>>(
            m, wt + lw + WOFF_W2, b2v, xbuf, xbuf, nullptr, NTOK, 512, 2048);
    }
}